// round 2
// baseline (speedup 1.0000x reference)
#include <cuda_runtime.h>

// Shape: [1, 8, 8, 8, 258, 258, 1] fp32
//   images = 512, each 258x258 = 66564 elems; total = 34,080,768 elems.
//
// Strategy: split work into
//   1) bulk kernel:  out = x * hm  (pure streaming multiply, float4, .cs hints)
//   2) fixup kernel: rewrite the 4 halo lines per image with remapped x:
//        w==0   -> x[h][1]     w==257 -> x[h][256]   (cols win at corners)
//        h==0   -> x[1][w]     h==257 -> x[256][w]   (w=1..256 only)
// Fixup runs after bulk on the same stream, overwriting the (wrong) edge
// values the bulk kernel wrote. Extra traffic ~10MB of 409MB total.

#define HW 258
#define IMG_ELEMS (HW * HW)   // 66564
#define TOTAL 34080768
#define TOTAL4 (TOTAL / 4)    // 8,520,192

__global__ __launch_bounds__(256)
void halo_bulk_kernel(const float4* __restrict__ x,
                      const float4* __restrict__ hm,
                      float4* __restrict__ out)
{
    int i = blockIdx.x * blockDim.x + threadIdx.x;
    if (i >= TOTAL4) return;
    float4 a = __ldcs(&x[i]);
    float4 b = __ldcs(&hm[i]);
    float4 r;
    r.x = a.x * b.x;
    r.y = a.y * b.y;
    r.z = a.z * b.z;
    r.w = a.w * b.w;
    __stcs(&out[i], r);
}

// Per image: 1028 fixup positions.
//   t in [0,258)     : (h=t,   w=0)    src=(h,1)
//   t in [258,516)   : (h=t-258, w=257) src=(h,256)
//   t in [516,772)   : (h=0,   w=t-515) src=(1,w)     w in 1..256
//   t in [772,1028)  : (h=257, w=t-771) src=(256,w)   w in 1..256
#define FIX_PER_IMG 1028
#define FIX_TOTAL (512 * FIX_PER_IMG)   // 526,336

__global__ __launch_bounds__(256)
void halo_fixup_kernel(const float* __restrict__ x,
                       const float* __restrict__ hm,
                       float* __restrict__ out)
{
    int gid = blockIdx.x * blockDim.x + threadIdx.x;
    if (gid >= FIX_TOTAL) return;
    int img = gid / FIX_PER_IMG;
    int t   = gid - img * FIX_PER_IMG;

    int h, w, sh, sw;
    if (t < 258)       { h = t;        w = 0;       sh = h;   sw = 1;   }
    else if (t < 516)  { h = t - 258;  w = HW - 1;  sh = h;   sw = 256; }
    else if (t < 772)  { h = 0;        w = t - 515; sh = 1;   sw = w;   }
    else               { h = HW - 1;   w = t - 771; sh = 256; sw = w;   }

    const float* xb = x + img * IMG_ELEMS;
    int didx = img * IMG_ELEMS + h * HW + w;
    out[didx] = xb[sh * HW + sw] * hm[didx];
}

extern "C" void kernel_launch(void* const* d_in, const int* in_sizes, int n_in,
                              void* d_out, int out_size)
{
    const float* x  = (const float*)d_in[0];
    const float* hm = (const float*)d_in[1];
    float* out = (float*)d_out;

    {
        const int threads = 256;
        const int blocks = (TOTAL4 + threads - 1) / threads;  // 33,282
        halo_bulk_kernel<<<blocks, threads>>>((const float4*)x,
                                              (const float4*)hm,
                                              (float4*)out);
    }
    {
        const int threads = 256;
        const int blocks = (FIX_TOTAL + threads - 1) / threads;  // 2,056
        halo_fixup_kernel<<<blocks, threads>>>(x, hm, out);
    }
}

// round 3
// speedup vs baseline: 1.0847x; 1.0847x over previous
#include <cuda_runtime.h>

// Shape: [1, 8, 8, 8, 258, 258, 1] fp32
//   images = 512, each 258x258 = 66564 elems; total = 34,080,768 elems.
//
// Single fused kernel. Hot path = pure streaming multiply (LDG.128 x,
// LDG.128 hm, 4xFMUL, STG.128). Only chunks touching a halo line
// (~3.8% of chunks) recompute their lanes with remapped scalar loads.
//
// Remap (all reads from ORIGINAL x; W-axis wins at corners):
//   w==0 -> (h,1)   w==257 -> (h,256)   else h==0 -> (1,w)   h==257 -> (256,w)

#define HW 258
#define IMG_ELEMS (HW * HW)   // 66564
#define TOTAL 34080768
#define TOTAL4 (TOTAL / 4)    // 8,520,192

__global__ __launch_bounds__(256)
void halo_fused_kernel(const float* __restrict__ x,
                       const float* __restrict__ hm,
                       float* __restrict__ out)
{
    unsigned i = blockIdx.x * blockDim.x + threadIdx.x;
    if (i >= TOTAL4) return;
    unsigned idx = i * 4u;

    // Unconditional vector loads (correct for interior chunks).
    float4 a = __ldcs(reinterpret_cast<const float4*>(x + idx));
    float4 b = __ldcs(reinterpret_cast<const float4*>(hm + idx));

    // Interior test: all 4 lanes in same row, cols 1..256, rows 1..256.
    unsigned img = idx / IMG_ELEMS;
    unsigned rem = idx - img * IMG_ELEMS;
    unsigned h0  = rem / HW;
    unsigned w0  = rem - h0 * HW;

    if (!((w0 - 1u) <= 252u && (h0 - 1u) <= 255u)) {
        // Slow path: per-lane remap. Lanes may straddle a row boundary.
        const float* xb = x + img * IMG_ELEMS;
        float lanes[4];
        unsigned h = h0, w = w0;
#pragma unroll
        for (int k = 0; k < 4; ++k) {
            unsigned sh = h, sw = w;
            if (w == 0u)           sw = 1u;
            else if (w == HW - 1u) sw = HW - 2u;
            else if (h == 0u)      sh = 1u;
            else if (h == HW - 1u) sh = HW - 2u;
            lanes[k] = xb[sh * HW + sw];
            if (++w == HW) { w = 0u; ++h; }
        }
        a.x = lanes[0]; a.y = lanes[1]; a.z = lanes[2]; a.w = lanes[3];
    }

    float4 r;
    r.x = a.x * b.x;
    r.y = a.y * b.y;
    r.z = a.z * b.z;
    r.w = a.w * b.w;
    __stcs(reinterpret_cast<float4*>(out + idx), r);
}

extern "C" void kernel_launch(void* const* d_in, const int* in_sizes, int n_in,
                              void* d_out, int out_size)
{
    const float* x  = (const float*)d_in[0];
    const float* hm = (const float*)d_in[1];
    float* out = (float*)d_out;

    const int threads = 256;
    const int blocks = (TOTAL4 + threads - 1) / threads;  // 33,282
    halo_fused_kernel<<<blocks, threads>>>(x, hm, out);
}